// round 11
// baseline (speedup 1.0000x reference)
#include <cuda_runtime.h>
#include <cuda_bf16.h>
#include <cstdint>
#include <cstddef>

// ---------------------------------------------------------------------------
// Problem constants (fixed by reference)
// ---------------------------------------------------------------------------
#define NN   10000     // nodes
#define BB   32        // batch
#define DIN  2
#define HH   64
#define GIN  66        // DIN + HH
#define CC   2112      // GIN * BB  (diffusion GEMM width)
#define KF   198

// ---------------------------------------------------------------------------
// Scratch: __device__ globals (no cudaMalloc allowed)
// ---------------------------------------------------------------------------
__device__ __nv_bfloat16 g_Abf[(size_t)NN * NN];          // 200 MB
__device__ float          g_X0f[(size_t)NN * CC];
__device__ __nv_bfloat16  g_X0b[(size_t)NN * CC];
__device__ float          g_X1f[(size_t)NN * CC];
__device__ __nv_bfloat16  g_X1b[(size_t)NN * CC];
__device__ float          g_X2f[(size_t)NN * CC];
__device__ float          g_r[(size_t)BB * NN * HH];
__device__ float          g_u[(size_t)BB * NN * HH];

// ---------------------------------------------------------------------------
// PTX helpers (baseline PTX only — harness targets compute_103, no 'a' feats)
// ---------------------------------------------------------------------------
__device__ __forceinline__ uint32_t smem_u32(const void* p) {
    uint32_t a;
    asm("{ .reg .u64 t; cvta.to.shared.u64 t, %1; cvt.u32.u64 %0, t; }"
        : "=r"(a) : "l"(p));
    return a;
}
__device__ __forceinline__ void cp_async16(uint32_t dst, const void* gsrc, bool pred) {
    int sz = pred ? 16 : 0;   // src-size 0 -> zero-fill 16B
    asm volatile("cp.async.cg.shared.global [%0], [%1], 16, %2;\n"
                 :: "r"(dst), "l"(gsrc), "r"(sz));
}
__device__ __forceinline__ void cp_commit() {
    asm volatile("cp.async.commit_group;\n" ::: "memory");
}
template <int NW>
__device__ __forceinline__ void cp_wait() {
    asm volatile("cp.async.wait_group %0;\n" :: "n"(NW) : "memory");
}
__device__ __forceinline__ void ldm_x4(uint32_t& r0, uint32_t& r1, uint32_t& r2, uint32_t& r3,
                                       uint32_t a) {
    asm volatile("ldmatrix.sync.aligned.m8n8.x4.shared.b16 {%0,%1,%2,%3}, [%4];"
                 : "=r"(r0), "=r"(r1), "=r"(r2), "=r"(r3) : "r"(a));
}
__device__ __forceinline__ void ldm_x4t(uint32_t& r0, uint32_t& r1, uint32_t& r2, uint32_t& r3,
                                        uint32_t a) {
    asm volatile("ldmatrix.sync.aligned.m8n8.x4.trans.shared.b16 {%0,%1,%2,%3}, [%4];"
                 : "=r"(r0), "=r"(r1), "=r"(r2), "=r"(r3) : "r"(a));
}
__device__ __forceinline__ void mma_bf16(float c[4],
                                         uint32_t a0, uint32_t a1, uint32_t a2, uint32_t a3,
                                         uint32_t b0, uint32_t b1) {
    asm volatile("mma.sync.aligned.m16n8k16.row.col.f32.bf16.bf16.f32 "
                 "{%0,%1,%2,%3}, {%4,%5,%6,%7}, {%8,%9}, {%0,%1,%2,%3};"
                 : "+f"(c[0]), "+f"(c[1]), "+f"(c[2]), "+f"(c[3])
                 : "r"(a0), "r"(a1), "r"(a2), "r"(a3), "r"(b0), "r"(b1));
}

// ---------------------------------------------------------------------------
// Kernel 0: convert A fp32 -> bf16 (vectorized)
// ---------------------------------------------------------------------------
__global__ void k_convA(const float4* __restrict__ A4) {
    const size_t n4 = (size_t)NN * NN / 4;
    size_t stride = (size_t)gridDim.x * blockDim.x;
    for (size_t i = (size_t)blockIdx.x * blockDim.x + threadIdx.x; i < n4; i += stride) {
        float4 v = A4[i];
        __nv_bfloat162 lo = __floats2bfloat162_rn(v.x, v.y);
        __nv_bfloat162 hi = __floats2bfloat162_rn(v.z, v.w);
        uint2 o;
        o.x = *reinterpret_cast<uint32_t*>(&lo);
        o.y = *reinterpret_cast<uint32_t*>(&hi);
        reinterpret_cast<uint2*>(g_Abf)[i] = o;
    }
}

// ---------------------------------------------------------------------------
// Kernel 1: build X0 [N, d*B+b] (fp32 + bf16). WITH_R -> states -> r*states
// ---------------------------------------------------------------------------
template <bool WITH_R>
__global__ void k_pack(const float* __restrict__ inputs, const float* __restrict__ states) {
    int i = blockIdx.x * blockDim.x + threadIdx.x;
    const int total = NN * CC;
    if (i >= total) return;
    int n = i / CC;
    int c = i - n * CC;
    int d = c >> 5;
    int b = c & 31;
    float v;
    if (d < DIN) {
        v = inputs[((size_t)b * NN + n) * DIN + d];
    } else {
        size_t idx = ((size_t)b * NN + n) * HH + (d - DIN);
        float s = states[idx];
        v = WITH_R ? g_r[idx] * s : s;
    }
    g_X0f[i] = v;
    g_X0b[i] = __float2bfloat16(v);
}

// ---------------------------------------------------------------------------
// Kernel 2: bf16 HMMA GEMM, CTA 128x128, 8 warps (2x4), warp tile 64x32,
//           K-stage 64, XOR-swizzled smem, 3-stage cp.async pipeline.
//   Cf = alpha*(A@B) + addScale*Add ; optional bf16 copy Cb.
// ---------------------------------------------------------------------------
#define GBM 128
#define GBN 128
#define GBK 64
#define NSTG 3
#define STG_BYTES 32768                    // A 16KB + B 16KB per stage
#define SMEM_GEMM (NSTG * STG_BYTES)       // 96 KB

__global__ __launch_bounds__(256, 2)
void k_gemm_bf16(const __nv_bfloat16* __restrict__ A,
                 const __nv_bfloat16* __restrict__ Bm,
                 float alpha,
                 const float* __restrict__ Add, float addScale,
                 float* __restrict__ Cf, __nv_bfloat16* __restrict__ Cb,
                 int Mrows, int Kdim, int Ncols) {
    extern __shared__ __align__(128) char smem_raw[];
    const uint32_t sbase = smem_u32(smem_raw);

    const int t = threadIdx.x;
    const int lane = t & 31;
    const int w = t >> 5;
    const int rowW = (w >> 2) * 64;     // 0 / 64
    const int colW = (w & 3) * 32;      // 0..96
    const int mBase = blockIdx.y * GBM;
    const int nBase = blockIdx.x * GBN;
    const int KT = (Kdim + GBK - 1) / GBK;

    // A smem: row(0..127) x 8 chunks of 16B; swizzle chunk ^= row&7
    // B smem: k(0..63) x 16 chunks of 16B; swizzle low3(chunk) ^= k&7
    auto loadTile = [&](int kt, int stg) {
        const int k0 = kt * GBK;
        const uint32_t aB = sbase + (uint32_t)stg * STG_BYTES;
        const uint32_t bB = aB + 16384;
#pragma unroll
        for (int i = 0; i < 4; i++) {               // A: 1024 x 16B
            int idx = t + i * 256;
            int r = idx >> 3, ch = idx & 7;
            int grow = mBase + r;
            int gk = k0 + ch * 8;
            bool p = (grow < Mrows) && (gk < Kdim);
            const __nv_bfloat16* src = A + (p ? (size_t)grow * Kdim + gk : 0);
            uint32_t dst = aB + (uint32_t)(r * 128 + ((ch ^ (r & 7)) << 4));
            cp_async16(dst, src, p);
        }
#pragma unroll
        for (int i = 0; i < 4; i++) {               // B: 1024 x 16B
            int idx = t + i * 256;
            int k = idx >> 4, ch = idx & 15;
            int gk = k0 + k;
            int gn = nBase + ch * 8;
            bool p = (gk < Kdim) && (gn < Ncols);
            const __nv_bfloat16* src = Bm + (p ? (size_t)gk * Ncols + gn : 0);
            int phys = (ch & 8) | ((ch ^ (k & 7)) & 7);
            uint32_t dst = bB + (uint32_t)(k * 256 + (phys << 4));
            cp_async16(dst, src, p);
        }
        cp_commit();
    };

    float acc[4][4][4];
#pragma unroll
    for (int mi = 0; mi < 4; mi++)
#pragma unroll
        for (int ni = 0; ni < 4; ni++)
#pragma unroll
            for (int q = 0; q < 4; q++) acc[mi][ni][q] = 0.f;

    loadTile(0, 0);
    if (1 < KT) loadTile(1, 1);

    // B ldmatrix x4.trans: lanes 0-15 -> 16 k-rows at chunk ch, lanes 16-31 ->
    // the same k-rows at chunk ch+1; frags {r0,r1} = col-chunk ch, {r2,r3} = ch+1.
    const int lk  = (lane & 15);
    const int lhi = (lane >> 4);

    for (int s = 0; s < KT; ++s) {
        if (s + 2 < KT) { loadTile(s + 2, (s + 2) % NSTG); cp_wait<2>(); }
        else if (s + 1 < KT) cp_wait<1>();
        else cp_wait<0>();
        __syncthreads();

        const uint32_t aB = sbase + (uint32_t)((s % NSTG) * STG_BYTES);
        const uint32_t bB = aB + 16384;
#pragma unroll
        for (int kk = 0; kk < GBK; kk += 16) {
            uint32_t a[4][4];
#pragma unroll
            for (int mi = 0; mi < 4; mi++) {
                int row = rowW + mi * 16 + (lane & 15);
                int ch = (kk >> 3) + (lane >> 4);
                ldm_x4(a[mi][0], a[mi][1], a[mi][2], a[mi][3],
                       aB + (uint32_t)(row * 128 + ((ch ^ (row & 7)) << 4)));
            }
            uint32_t b[4][2];
#pragma unroll
            for (int pr = 0; pr < 2; pr++) {
                int ch = (colW >> 3) + pr * 2 + lhi;
                int k = kk + lk;
                int phys = (ch & 8) | ((ch ^ (k & 7)) & 7);
                ldm_x4t(b[pr * 2][0], b[pr * 2][1], b[pr * 2 + 1][0], b[pr * 2 + 1][1],
                        bB + (uint32_t)(k * 256 + (phys << 4)));
            }
#pragma unroll
            for (int mi = 0; mi < 4; mi++)
#pragma unroll
                for (int ni = 0; ni < 4; ni++)
                    mma_bf16(acc[mi][ni], a[mi][0], a[mi][1], a[mi][2], a[mi][3],
                             b[ni][0], b[ni][1]);
        }
        __syncthreads();
    }

    // Epilogue (identical layout to the R9-passing version)
    auto storeC = [&](int r, int c, float v) {
        if (r < Mrows && c < Ncols) {
            size_t o = (size_t)r * Ncols + c;
            float x = alpha * v;
            if (Add) x += addScale * Add[o];
            Cf[o] = x;
            if (Cb) Cb[o] = __float2bfloat16(x);
        }
    };
#pragma unroll
    for (int mi = 0; mi < 4; mi++) {
#pragma unroll
        for (int ni = 0; ni < 4; ni++) {
            int r0 = mBase + rowW + mi * 16 + (lane >> 2);
            int c0 = nBase + colW + ni * 8 + (lane & 3) * 2;
            storeC(r0,     c0,     acc[mi][ni][0]);
            storeC(r0,     c0 + 1, acc[mi][ni][1]);
            storeC(r0 + 8, c0,     acc[mi][ni][2]);
            storeC(r0 + 8, c0 + 1, acc[mi][ni][3]);
        }
    }
}

// ---------------------------------------------------------------------------
// Kernel 3: fp32 gate GEMM (unchanged, proven)
// ---------------------------------------------------------------------------
template <int OUT, bool IS_RU>
__global__ __launch_bounds__(256)
void k_gate(const float* __restrict__ W, const float* __restrict__ bias,
            const float* __restrict__ states, float* __restrict__ out) {
    constexpr int KC  = 33;
    constexpr int CG  = OUT / 8;
    constexpr int RPT = CG / 2;
    __shared__ __align__(16) float sW[KC][OUT];
    __shared__ float sF[128][KC];

    const int t = threadIdx.x;
    const int tc = t % CG;
    const int tr = t / CG;
    const int rowBase = blockIdx.x * 128;

    float acc[RPT][8];
#pragma unroll
    for (int i = 0; i < RPT; i++)
#pragma unroll
        for (int j = 0; j < 8; j++) acc[i][j] = 0.f;

    for (int kc = 0; kc < 6; ++kc) {
        for (int idx = t; idx < KC * OUT; idx += 256) {
            int kk = idx / OUT, o = idx - kk * OUT;
            sW[kk][o] = W[(size_t)(kc * KC + kk) * OUT + o];
        }
        for (int e = t; e < KC * 128; e += 256) {
            int row = e & 127;
            int kkpos = e >> 7;
            int k = kc * KC + kkpos;
            int m = k % 3;
            int d = k / 3;
            int grow = rowBase + row;
            int n = grow >> 5;
            int b = grow & 31;
            const float* X = (m == 0) ? g_X0f : ((m == 1) ? g_X1f : g_X2f);
            sF[row][kkpos] = X[(size_t)n * CC + d * 32 + b];
        }
        __syncthreads();
#pragma unroll 4
        for (int kk = 0; kk < KC; kk++) {
            float4 w0 = *reinterpret_cast<const float4*>(&sW[kk][tc * 8]);
            float4 w1 = *reinterpret_cast<const float4*>(&sW[kk][tc * 8 + 4]);
            float f[RPT];
#pragma unroll
            for (int i = 0; i < RPT; i++) f[i] = sF[tr * RPT + i][kk];
#pragma unroll
            for (int i = 0; i < RPT; i++) {
                acc[i][0] += f[i] * w0.x;  acc[i][1] += f[i] * w0.y;
                acc[i][2] += f[i] * w0.z;  acc[i][3] += f[i] * w0.w;
                acc[i][4] += f[i] * w1.x;  acc[i][5] += f[i] * w1.y;
                acc[i][6] += f[i] * w1.z;  acc[i][7] += f[i] * w1.w;
            }
        }
        __syncthreads();
    }

#pragma unroll
    for (int i = 0; i < RPT; i++) {
        int grow = rowBase + tr * RPT + i;
        int n = grow >> 5;
        int b = grow & 31;
#pragma unroll
        for (int j = 0; j < 8; j++) {
            int o = tc * 8 + j;
            float v = acc[i][j] + bias[o];
            if (IS_RU) {
                float s = 1.f / (1.f + expf(-v));
                if (o < HH) g_r[((size_t)b * NN + n) * HH + o] = s;
                else        g_u[((size_t)b * NN + n) * HH + (o - HH)] = s;
            } else {
                float c = tanhf(v);
                size_t idx = ((size_t)b * NN + n) * HH + o;
                float u = g_u[idx];
                out[idx] = u * states[idx] + (1.f - u) * c;
            }
        }
    }
}

// ---------------------------------------------------------------------------
// Launch
// ---------------------------------------------------------------------------
extern "C" void kernel_launch(void* const* d_in, const int* in_sizes, int n_in,
                              void* d_out, int out_size) {
    const float* inputs = (const float*)d_in[0];
    const float* states = (const float*)d_in[1];
    const float* A      = (const float*)d_in[2];
    const float* W_ru   = (const float*)d_in[3];
    const float* b_ru   = (const float*)d_in[4];
    const float* W_c    = (const float*)d_in[5];
    const float* b_c    = (const float*)d_in[6];
    float* out = (float*)d_out;

    void *pAbf, *pX0f, *pX0b, *pX1f, *pX1b, *pX2f;
    cudaGetSymbolAddress(&pAbf, g_Abf);
    cudaGetSymbolAddress(&pX0f, g_X0f);
    cudaGetSymbolAddress(&pX0b, g_X0b);
    cudaGetSymbolAddress(&pX1f, g_X1f);
    cudaGetSymbolAddress(&pX1b, g_X1b);
    cudaGetSymbolAddress(&pX2f, g_X2f);

    cudaFuncSetAttribute(k_gemm_bf16,
                         cudaFuncAttributeMaxDynamicSharedMemorySize, SMEM_GEMM);

    const dim3 gGrid((CC + GBN - 1) / GBN, (NN + GBM - 1) / GBM);  // 17 x 79
    const int packBlocks = (NN * CC + 255) / 256;
    const int gateBlocks = (BB * NN) / 128;

    k_convA<<<4096, 256>>>((const float4*)A);

    // ---- gconv 1 (r, u) ----
    k_pack<false><<<packBlocks, 256>>>(inputs, states);
    k_gemm_bf16<<<gGrid, 256, SMEM_GEMM>>>((const __nv_bfloat16*)pAbf,
                                           (const __nv_bfloat16*)pX0b,
                                           1.f, nullptr, 0.f,
                                           (float*)pX1f, (__nv_bfloat16*)pX1b,
                                           NN, NN, CC);
    k_gemm_bf16<<<gGrid, 256, SMEM_GEMM>>>((const __nv_bfloat16*)pAbf,
                                           (const __nv_bfloat16*)pX1b,
                                           2.f, (const float*)pX0f, -1.f,
                                           (float*)pX2f, nullptr, NN, NN, CC);
    k_gate<128, true><<<gateBlocks, 256>>>(W_ru, b_ru, nullptr, nullptr);

    // ---- gconv 2 (c) + final output ----
    k_pack<true><<<packBlocks, 256>>>(inputs, states);
    k_gemm_bf16<<<gGrid, 256, SMEM_GEMM>>>((const __nv_bfloat16*)pAbf,
                                           (const __nv_bfloat16*)pX0b,
                                           1.f, nullptr, 0.f,
                                           (float*)pX1f, (__nv_bfloat16*)pX1b,
                                           NN, NN, CC);
    k_gemm_bf16<<<gGrid, 256, SMEM_GEMM>>>((const __nv_bfloat16*)pAbf,
                                           (const __nv_bfloat16*)pX1b,
                                           2.f, (const float*)pX0f, -1.f,
                                           (float*)pX2f, nullptr, NN, NN, CC);
    k_gate<64, false><<<gateBlocks, 256>>>(W_c, b_c, states, out);
}

// round 13
// speedup vs baseline: 1.4693x; 1.4693x over previous
#include <cuda_runtime.h>
#include <cuda_bf16.h>
#include <cstdint>
#include <cstddef>

// ---------------------------------------------------------------------------
// Problem constants (fixed by reference)
// ---------------------------------------------------------------------------
#define NN   10000     // nodes
#define BB   32        // batch
#define DIN  2
#define HH   64
#define GIN  66        // DIN + HH
#define CC   2112      // GIN * BB  (diffusion GEMM width)
#define KF   198

// ---------------------------------------------------------------------------
// Scratch: __device__ globals (no cudaMalloc allowed)
// ---------------------------------------------------------------------------
__device__ __nv_bfloat16 g_Abf[(size_t)NN * NN];          // 200 MB
__device__ float          g_X0f[(size_t)NN * CC];
__device__ __nv_bfloat16  g_X0b[(size_t)NN * CC];
__device__ float          g_X1f[(size_t)NN * CC];
__device__ __nv_bfloat16  g_X1b[(size_t)NN * CC];
__device__ float          g_X2f[(size_t)NN * CC];
__device__ float          g_r[(size_t)BB * NN * HH];
__device__ float          g_u[(size_t)BB * NN * HH];

// ---------------------------------------------------------------------------
// PTX helpers (baseline PTX only — harness targets compute_103, no 'a' feats)
// ---------------------------------------------------------------------------
__device__ __forceinline__ uint32_t smem_u32(const void* p) {
    uint32_t a;
    asm("{ .reg .u64 t; cvta.to.shared.u64 t, %1; cvt.u32.u64 %0, t; }"
        : "=r"(a) : "l"(p));
    return a;
}
__device__ __forceinline__ void cp_async16(uint32_t dst, const void* gsrc, bool pred) {
    int sz = pred ? 16 : 0;   // src-size 0 -> zero-fill 16B
    asm volatile("cp.async.cg.shared.global [%0], [%1], 16, %2;\n"
                 :: "r"(dst), "l"(gsrc), "r"(sz));
}
__device__ __forceinline__ void cp_commit() {
    asm volatile("cp.async.commit_group;\n" ::: "memory");
}
template <int NW>
__device__ __forceinline__ void cp_wait() {
    asm volatile("cp.async.wait_group %0;\n" :: "n"(NW) : "memory");
}
__device__ __forceinline__ void ldm_x4(uint32_t& r0, uint32_t& r1, uint32_t& r2, uint32_t& r3,
                                       uint32_t a) {
    asm volatile("ldmatrix.sync.aligned.m8n8.x4.shared.b16 {%0,%1,%2,%3}, [%4];"
                 : "=r"(r0), "=r"(r1), "=r"(r2), "=r"(r3) : "r"(a));
}
__device__ __forceinline__ void ldm_x2t(uint32_t& r0, uint32_t& r1, uint32_t a) {
    asm volatile("ldmatrix.sync.aligned.m8n8.x2.trans.shared.b16 {%0,%1}, [%2];"
                 : "=r"(r0), "=r"(r1) : "r"(a));
}
__device__ __forceinline__ void mma_bf16(float c[4],
                                         uint32_t a0, uint32_t a1, uint32_t a2, uint32_t a3,
                                         uint32_t b0, uint32_t b1) {
    asm volatile("mma.sync.aligned.m16n8k16.row.col.f32.bf16.bf16.f32 "
                 "{%0,%1,%2,%3}, {%4,%5,%6,%7}, {%8,%9}, {%0,%1,%2,%3};"
                 : "+f"(c[0]), "+f"(c[1]), "+f"(c[2]), "+f"(c[3])
                 : "r"(a0), "r"(a1), "r"(a2), "r"(a3), "r"(b0), "r"(b1));
}

// ---------------------------------------------------------------------------
// Kernel 0: convert A fp32 -> bf16 (vectorized)
// ---------------------------------------------------------------------------
__global__ void k_convA(const float4* __restrict__ A4) {
    const size_t n4 = (size_t)NN * NN / 4;
    size_t stride = (size_t)gridDim.x * blockDim.x;
    for (size_t i = (size_t)blockIdx.x * blockDim.x + threadIdx.x; i < n4; i += stride) {
        float4 v = A4[i];
        __nv_bfloat162 lo = __floats2bfloat162_rn(v.x, v.y);
        __nv_bfloat162 hi = __floats2bfloat162_rn(v.z, v.w);
        uint2 o;
        o.x = *reinterpret_cast<uint32_t*>(&lo);
        o.y = *reinterpret_cast<uint32_t*>(&hi);
        reinterpret_cast<uint2*>(g_Abf)[i] = o;
    }
}

// ---------------------------------------------------------------------------
// Kernel 1: build X0 [N, d*B+b] (fp32 + bf16). WITH_R -> states -> r*states
// ---------------------------------------------------------------------------
template <bool WITH_R>
__global__ void k_pack(const float* __restrict__ inputs, const float* __restrict__ states) {
    int i = blockIdx.x * blockDim.x + threadIdx.x;
    const int total = NN * CC;
    if (i >= total) return;
    int n = i / CC;
    int c = i - n * CC;
    int d = c >> 5;
    int b = c & 31;
    float v;
    if (d < DIN) {
        v = inputs[((size_t)b * NN + n) * DIN + d];
    } else {
        size_t idx = ((size_t)b * NN + n) * HH + (d - DIN);
        float s = states[idx];
        v = WITH_R ? g_r[idx] * s : s;
    }
    g_X0f[i] = v;
    g_X0b[i] = __float2bfloat16(v);
}

// ---------------------------------------------------------------------------
// Kernel 2: bf16 HMMA GEMM, CTA 128x128, 8 warps (2x4), warp tile 64x32,
//           K-stage 96, XOR-swizzled smem, 2-stage cp.async double buffer.
//   A smem: 128 rows x 16 chunks (12 used) of 16B, pitch 256B.
//   B smem: 96 k-rows x 16 chunks of 16B, pitch 256B.
//   Cf = alpha*(A@B) + addScale*Add ; optional bf16 copy Cb.
// ---------------------------------------------------------------------------
#define GBM 128
#define GBN 128
#define GBK 96
#define A_STG 32768                         // 128 * 256B
#define B_STG 24576                         // 96 * 256B
#define STG_BYTES (A_STG + B_STG)           // 57344
#define SMEM_GEMM (2 * STG_BYTES)           // 114688

__global__ __launch_bounds__(256, 2)
void k_gemm_bf16(const __nv_bfloat16* __restrict__ A,
                 const __nv_bfloat16* __restrict__ Bm,
                 float alpha,
                 const float* __restrict__ Add, float addScale,
                 float* __restrict__ Cf, __nv_bfloat16* __restrict__ Cb,
                 int Mrows, int Kdim, int Ncols) {
    extern __shared__ __align__(128) char smem_raw[];
    const uint32_t sbase = smem_u32(smem_raw);

    const int t = threadIdx.x;
    const int lane = t & 31;
    const int w = t >> 5;
    const int rowW = (w >> 2) * 64;     // 0 / 64
    const int colW = (w & 3) * 32;      // 0..96
    const int mBase = blockIdx.y * GBM;
    const int nBase = blockIdx.x * GBN;
    const int KT = (Kdim + GBK - 1) / GBK;

    // A smem: row r, chunk ch(0..11): phys = (ch&8)|((ch^(r&7))&7), off r*256+phys*16
    // B smem: k-row k, chunk ch(0..15): phys = (ch&8)|((ch^(k&7))&7), off k*256+phys*16
    auto loadTile = [&](int kt, int stg) {
        const int k0 = kt * GBK;
        const uint32_t aB = sbase + (uint32_t)stg * STG_BYTES;
        const uint32_t bB = aB + A_STG;
#pragma unroll
        for (int i = 0; i < 8; i++) {               // A: 128 rows x 12 chunks (of 16 slots)
            int idx = t + i * 256;
            int r = idx >> 4, ch = idx & 15;
            if (ch < 12) {
                int grow = mBase + r;
                int gk = k0 + ch * 8;
                bool p = (grow < Mrows) && (gk < Kdim);
                const __nv_bfloat16* src = A + (p ? (size_t)grow * Kdim + gk : 0);
                int phys = (ch & 8) | ((ch ^ (r & 7)) & 7);
                uint32_t dst = aB + (uint32_t)(r * 256 + (phys << 4));
                cp_async16(dst, src, p);
            }
        }
#pragma unroll
        for (int i = 0; i < 6; i++) {               // B: 96 k-rows x 16 chunks
            int idx = t + i * 256;
            int k = idx >> 4, ch = idx & 15;
            int gk = k0 + k;
            int gn = nBase + ch * 8;
            bool p = (gk < Kdim) && (gn < Ncols);
            const __nv_bfloat16* src = Bm + (p ? (size_t)gk * Ncols + gn : 0);
            int phys = (ch & 8) | ((ch ^ (k & 7)) & 7);
            uint32_t dst = bB + (uint32_t)(k * 256 + (phys << 4));
            cp_async16(dst, src, p);
        }
        cp_commit();
    };

    float acc[4][4][4];
#pragma unroll
    for (int mi = 0; mi < 4; mi++)
#pragma unroll
        for (int ni = 0; ni < 4; ni++)
#pragma unroll
            for (int q = 0; q < 4; q++) acc[mi][ni][q] = 0.f;

    loadTile(0, 0);

    for (int kt = 0; kt < KT; ++kt) {
        if (kt + 1 < KT) {
            loadTile(kt + 1, (kt + 1) & 1);
            cp_wait<1>();
        } else {
            cp_wait<0>();
        }
        __syncthreads();
        const int buf = kt & 1;
        const uint32_t aB = sbase + (uint32_t)buf * STG_BYTES;
        const uint32_t bB = aB + A_STG;
#pragma unroll
        for (int kk = 0; kk < GBK; kk += 16) {
            uint32_t a[4][4];
#pragma unroll
            for (int mi = 0; mi < 4; mi++) {
                int row = rowW + mi * 16 + (lane & 15);
                int ch = (kk >> 3) + (lane >> 4);
                int phys = (ch & 8) | ((ch ^ (row & 7)) & 7);
                ldm_x4(a[mi][0], a[mi][1], a[mi][2], a[mi][3],
                       aB + (uint32_t)(row * 256 + (phys << 4)));
            }
            uint32_t b[4][2];
#pragma unroll
            for (int ni = 0; ni < 4; ni++) {
                int k = kk + (lane & 15);
                int ch = (colW >> 3) + ni;
                int phys = (ch & 8) | ((ch ^ (k & 7)) & 7);
                ldm_x2t(b[ni][0], b[ni][1],
                        bB + (uint32_t)(k * 256 + (phys << 4)));
            }
#pragma unroll
            for (int mi = 0; mi < 4; mi++)
#pragma unroll
                for (int ni = 0; ni < 4; ni++)
                    mma_bf16(acc[mi][ni], a[mi][0], a[mi][1], a[mi][2], a[mi][3],
                             b[ni][0], b[ni][1]);
        }
        __syncthreads();
    }

    // Epilogue (identical layout to the R9-passing version)
    auto storeC = [&](int r, int c, float v) {
        if (r < Mrows && c < Ncols) {
            size_t o = (size_t)r * Ncols + c;
            float x = alpha * v;
            if (Add) x += addScale * Add[o];
            Cf[o] = x;
            if (Cb) Cb[o] = __float2bfloat16(x);
        }
    };
#pragma unroll
    for (int mi = 0; mi < 4; mi++) {
#pragma unroll
        for (int ni = 0; ni < 4; ni++) {
            int r0 = mBase + rowW + mi * 16 + (lane >> 2);
            int c0 = nBase + colW + ni * 8 + (lane & 3) * 2;
            storeC(r0,     c0,     acc[mi][ni][0]);
            storeC(r0,     c0 + 1, acc[mi][ni][1]);
            storeC(r0 + 8, c0,     acc[mi][ni][2]);
            storeC(r0 + 8, c0 + 1, acc[mi][ni][3]);
        }
    }
}

// ---------------------------------------------------------------------------
// Kernel 3: fp32 gate GEMM (unchanged, proven)
// ---------------------------------------------------------------------------
template <int OUT, bool IS_RU>
__global__ __launch_bounds__(256)
void k_gate(const float* __restrict__ W, const float* __restrict__ bias,
            const float* __restrict__ states, float* __restrict__ out) {
    constexpr int KC  = 33;
    constexpr int CG  = OUT / 8;
    constexpr int RPT = CG / 2;
    __shared__ __align__(16) float sW[KC][OUT];
    __shared__ float sF[128][KC];

    const int t = threadIdx.x;
    const int tc = t % CG;
    const int tr = t / CG;
    const int rowBase = blockIdx.x * 128;

    float acc[RPT][8];
#pragma unroll
    for (int i = 0; i < RPT; i++)
#pragma unroll
        for (int j = 0; j < 8; j++) acc[i][j] = 0.f;

    for (int kc = 0; kc < 6; ++kc) {
        for (int idx = t; idx < KC * OUT; idx += 256) {
            int kk = idx / OUT, o = idx - kk * OUT;
            sW[kk][o] = W[(size_t)(kc * KC + kk) * OUT + o];
        }
        for (int e = t; e < KC * 128; e += 256) {
            int row = e & 127;
            int kkpos = e >> 7;
            int k = kc * KC + kkpos;
            int m = k % 3;
            int d = k / 3;
            int grow = rowBase + row;
            int n = grow >> 5;
            int b = grow & 31;
            const float* X = (m == 0) ? g_X0f : ((m == 1) ? g_X1f : g_X2f);
            sF[row][kkpos] = X[(size_t)n * CC + d * 32 + b];
        }
        __syncthreads();
#pragma unroll 4
        for (int kk = 0; kk < KC; kk++) {
            float4 w0 = *reinterpret_cast<const float4*>(&sW[kk][tc * 8]);
            float4 w1 = *reinterpret_cast<const float4*>(&sW[kk][tc * 8 + 4]);
            float f[RPT];
#pragma unroll
            for (int i = 0; i < RPT; i++) f[i] = sF[tr * RPT + i][kk];
#pragma unroll
            for (int i = 0; i < RPT; i++) {
                acc[i][0] += f[i] * w0.x;  acc[i][1] += f[i] * w0.y;
                acc[i][2] += f[i] * w0.z;  acc[i][3] += f[i] * w0.w;
                acc[i][4] += f[i] * w1.x;  acc[i][5] += f[i] * w1.y;
                acc[i][6] += f[i] * w1.z;  acc[i][7] += f[i] * w1.w;
            }
        }
        __syncthreads();
    }

#pragma unroll
    for (int i = 0; i < RPT; i++) {
        int grow = rowBase + tr * RPT + i;
        int n = grow >> 5;
        int b = grow & 31;
#pragma unroll
        for (int j = 0; j < 8; j++) {
            int o = tc * 8 + j;
            float v = acc[i][j] + bias[o];
            if (IS_RU) {
                float s = 1.f / (1.f + expf(-v));
                if (o < HH) g_r[((size_t)b * NN + n) * HH + o] = s;
                else        g_u[((size_t)b * NN + n) * HH + (o - HH)] = s;
            } else {
                float c = tanhf(v);
                size_t idx = ((size_t)b * NN + n) * HH + o;
                float u = g_u[idx];
                out[idx] = u * states[idx] + (1.f - u) * c;
            }
        }
    }
}

// ---------------------------------------------------------------------------
// Launch
// ---------------------------------------------------------------------------
extern "C" void kernel_launch(void* const* d_in, const int* in_sizes, int n_in,
                              void* d_out, int out_size) {
    const float* inputs = (const float*)d_in[0];
    const float* states = (const float*)d_in[1];
    const float* A      = (const float*)d_in[2];
    const float* W_ru   = (const float*)d_in[3];
    const float* b_ru   = (const float*)d_in[4];
    const float* W_c    = (const float*)d_in[5];
    const float* b_c    = (const float*)d_in[6];
    float* out = (float*)d_out;

    void *pAbf, *pX0f, *pX0b, *pX1f, *pX1b, *pX2f;
    cudaGetSymbolAddress(&pAbf, g_Abf);
    cudaGetSymbolAddress(&pX0f, g_X0f);
    cudaGetSymbolAddress(&pX0b, g_X0b);
    cudaGetSymbolAddress(&pX1f, g_X1f);
    cudaGetSymbolAddress(&pX1b, g_X1b);
    cudaGetSymbolAddress(&pX2f, g_X2f);

    cudaFuncSetAttribute(k_gemm_bf16,
                         cudaFuncAttributeMaxDynamicSharedMemorySize, SMEM_GEMM);

    const dim3 gGrid((CC + GBN - 1) / GBN, (NN + GBM - 1) / GBM);  // 17 x 79
    const int packBlocks = (NN * CC + 255) / 256;
    const int gateBlocks = (BB * NN) / 128;

    k_convA<<<4096, 256>>>((const float4*)A);

    // ---- gconv 1 (r, u) ----
    k_pack<false><<<packBlocks, 256>>>(inputs, states);
    k_gemm_bf16<<<gGrid, 256, SMEM_GEMM>>>((const __nv_bfloat16*)pAbf,
                                           (const __nv_bfloat16*)pX0b,
                                           1.f, nullptr, 0.f,
                                           (float*)pX1f, (__nv_bfloat16*)pX1b,
                                           NN, NN, CC);
    k_gemm_bf16<<<gGrid, 256, SMEM_GEMM>>>((const __nv_bfloat16*)pAbf,
                                           (const __nv_bfloat16*)pX1b,
                                           2.f, (const float*)pX0f, -1.f,
                                           (float*)pX2f, nullptr, NN, NN, CC);
    k_gate<128, true><<<gateBlocks, 256>>>(W_ru, b_ru, nullptr, nullptr);

    // ---- gconv 2 (c) + final output ----
    k_pack<true><<<packBlocks, 256>>>(inputs, states);
    k_gemm_bf16<<<gGrid, 256, SMEM_GEMM>>>((const __nv_bfloat16*)pAbf,
                                           (const __nv_bfloat16*)pX0b,
                                           1.f, nullptr, 0.f,
                                           (float*)pX1f, (__nv_bfloat16*)pX1b,
                                           NN, NN, CC);
    k_gemm_bf16<<<gGrid, 256, SMEM_GEMM>>>((const __nv_bfloat16*)pAbf,
                                           (const __nv_bfloat16*)pX1b,
                                           2.f, (const float*)pX0f, -1.f,
                                           (float*)pX2f, nullptr, NN, NN, CC);
    k_gate<64, false><<<gateBlocks, 256>>>(W_c, b_c, states, out);
}